// round 5
// baseline (speedup 1.0000x reference)
#include <cuda_runtime.h>
#include <cstdint>

// x: [B=8, Ci=32, T=128, X=256, P=3] f32
// w*: [Ci=32, Co=32, 16, 16, 3] f32
// out: [8, 32, 128, 256, 3] f32
#define B_  8
#define CI_ 32
#define CO_ 32
#define T_  128
#define X_  256
#define P_  3

__device__ float2 g_C[1024*256];     // [mode][bci]   2 MB
__device__ float2 g_D[256*1024];     // [bco][mode]   2 MB
__device__ float2 g_W[1024*1024];    // [mode][e=ci*32+co]  8 MB

__device__ __forceinline__ float2 cmulf(float2 a, float2 b) {
    return make_float2(a.x*b.x - a.y*b.y, a.x*b.y + a.y*b.x);
}

// In-register radix-2 FFT-16. SGN=-1: forward; SGN=+1: inverse (unscaled).
template<int SGN>
__device__ __forceinline__ void fft16(float2 v[16]) {
    float2 tmp;
#define SW_(i,j) { tmp=v[i]; v[i]=v[j]; v[j]=tmp; }
    SW_(1,8) SW_(2,4) SW_(3,12) SW_(5,10) SW_(7,14) SW_(11,13)
#undef SW_
    const float Ct[8] = {1.f, 0.92387953251f, 0.70710678119f, 0.38268343236f,
                         0.f, -0.38268343236f, -0.70710678119f, -0.92387953251f};
    const float St[8] = {0.f, 0.38268343236f, 0.70710678119f, 0.92387953251f,
                         1.f, 0.92387953251f, 0.70710678119f, 0.38268343236f};
#pragma unroll
    for (int m = 2; m <= 16; m <<= 1) {
        const int half = m >> 1;
        const int step = 16 / m;
#pragma unroll
        for (int k0 = 0; k0 < 16; k0 += m) {
#pragma unroll
            for (int j = 0; j < half; j++) {
                float2 wt = make_float2(Ct[j*step], (float)SGN * St[j*step]);
                float2 t = cmulf(v[k0+j+half], wt);
                float2 u = v[k0+j];
                v[k0+j]      = make_float2(u.x + t.x, u.y + t.y);
                v[k0+j+half] = make_float2(u.x - t.x, u.y - t.y);
            }
        }
    }
}

// ---------------------------------------------------------------------------
// K0: weight transpose: w{1,2}_{re,im}[ci][co][kt16][kx16][kp3]
//   -> g_W[mode = kt32*32 + kx*2 + kp][e = ci*32+co] (float2, coalesced writes)
// grid (32 kt, 32 e-tiles), 256 threads.
// ---------------------------------------------------------------------------
__global__ void __launch_bounds__(256) k_wt(const float* __restrict__ w1r, const float* __restrict__ w1i,
                                           const float* __restrict__ w2r, const float* __restrict__ w2i) {
    __shared__ float sre[32][49];
    __shared__ float sim[32][49];
    const int kt = blockIdx.x;          // 0..31
    const int e0 = blockIdx.y * 32;
    const float* wr = (kt < 16) ? w1r : w2r;
    const float* wi = (kt < 16) ? w1i : w2i;
    const int ktw = kt & 15;
    const int tid = threadIdx.x;
    for (int j = tid; j < 32*48; j += 256) {
        int el = j / 48, m = j % 48;
        size_t src = (size_t)(e0 + el)*768 + ktw*48 + m;
        sre[el][m] = wr[src];
        sim[el][m] = wi[src];
    }
    __syncthreads();
    for (int idx = tid; idx < 1024; idx += 256) {
        int ml = idx >> 5, el = idx & 31;    // ml = kx*2+kp
        int kx = ml >> 1, kp = ml & 1;
        int m = kx*3 + kp;
        g_W[((size_t)kt*32 + ml)*1024 + e0 + el] = make_float2(sre[el][m], sim[el][m]);
    }
}

// ---------------------------------------------------------------------------
// K_fwd: fused forward. Block = one bci (256 blocks, 256 threads).
//  Loop over 16 chunks of 8 t-rows:
//    stage rows -> P-stage (rfft3->2) + pruned X-DFT (256->16) -> Asm[t][rem]
//  Then radix-split T-DFT (128 -> 32 corner modes) -> g_C[mode][bci]
// ---------------------------------------------------------------------------
__global__ void __launch_bounds__(256) k_fwd(const float* __restrict__ x) {
    extern __shared__ float2 dyn[];
    float2* region = dyn;            // [8][544]  staging / per-warp fb union
    float2* Asm    = dyn + 8*544;    // [128][34] : Asm[t][rem]
    __shared__ float2 tw[256];       // e^{-2pi i n/256}
    __shared__ float2 tab[128];      // e^{-2pi i n/128}
    __shared__ float2 outst[8][32];

    const int tid = threadIdx.x;
    {
        float sv, cv;
        __sincosf(-6.283185307179586f * (float)tid * (1.0f/256.0f), &sv, &cv);
        tw[tid] = make_float2(cv, sv);
        if (tid < 128) {
            __sincosf(-6.283185307179586f * (float)tid * (1.0f/128.0f), &sv, &cv);
            tab[tid] = make_float2(cv, sv);
        }
    }
    const int bci = blockIdx.x;
    const int w  = tid >> 5;
    const int ln = tid & 31;
    const int b_ = ln & 15;
    const int kp = ln >> 4;

    for (int c = 0; c < 16; c++) {
        const int t0 = c * 8;
        // stage 8 rows x 768 floats, coalesced
        const float4* src = (const float4*)(x + ((size_t)bci*T_ + t0) * 768);
#pragma unroll
        for (int i = 0; i < 6; i++) {
            int idx = tid + i*256;
            float4 vv = src[idx];
            int fl = idx * 4;
            int line = fl / 768, off = fl % 768;
            *(float4*)((float*)(region + line*544) + off) = vv;
        }
        __syncthreads();

        // P-stage + X-DFT on line t0+w (warp w)
        const float* rp = (const float*)(region + w*544);
        float2 v[16];
#pragma unroll
        for (int a = 0; a < 16; a++) {
            int base = (a*16 + b_) * 3;
            float xa = rp[base], xb = rp[base+1], xc = rp[base+2];
            if (kp == 0) v[a] = make_float2(xa + xb + xc, 0.f);
            else         v[a] = make_float2(xa - 0.5f*(xb+xc), 0.8660254037844386f*(xc - xb));
        }
        __syncwarp();
        fft16<-1>(v);

        float2* trb = region + w*544;
#pragma unroll
        for (int k = 0; k < 16; k++)
            trb[b_*33 + kp*16 + k] = cmulf(v[k], tw[b_*k]);
        __syncwarp();

        const int ko = ln & 15, kpo = ln >> 4;
        float2 acc = make_float2(0.f, 0.f);
#pragma unroll
        for (int b = 0; b < 16; b++) {
            float2 z = trb[b*33 + kpo*16 + ko];
            acc.x += z.x; acc.y += z.y;
        }
        outst[w][ln] = acc;
        __syncthreads();

        // copy to Asm[t][rem], rem = ko*2 + kpo
        {
            int rem = tid & 31, tt = tid >> 5;
            Asm[(t0 + tt)*34 + rem] = outst[tt][(rem & 1)*16 + (rem >> 1)];
        }
        // no extra sync: next staging writes region only (outst overwritten after next sync)
    }
    __syncthreads();

    // ---- T-DFT (radix split t = 8a+b), 8 warps x 4 rem-lines ----
    const int l = ln >> 3, b = ln & 7;
    float2 v[16];
#pragma unroll
    for (int a = 0; a < 16; a++)
        v[a] = Asm[(a*8 + b)*34 + (w*4 + l)];
    __syncwarp();
    fft16<-1>(v);
    float2* fb = region + w*544;      // 32*17 = 544 exactly
#pragma unroll
    for (int k = 0; k < 16; k++)
        fb[(l*8 + b)*17 + k] = v[k];
    __syncwarp();

    const int o  = ln;
    const int f  = (o < 16) ? o : (o + 96);
    const int km = o & 15;
    float2 acc[4];
#pragma unroll
    for (int q = 0; q < 4; q++) acc[q] = make_float2(0.f, 0.f);
#pragma unroll
    for (int bb = 0; bb < 8; bb++) {
        float2 twv = tab[(bb*f) & 127];
#pragma unroll
        for (int q = 0; q < 4; q++) {
            float2 z = fb[(q*8 + bb)*17 + km];
            acc[q].x += z.x*twv.x - z.y*twv.y;
            acc[q].y += z.x*twv.y + z.y*twv.x;
        }
    }
#pragma unroll
    for (int q = 0; q < 4; q++)
        g_C[((size_t)o*32 + (w*4 + q))*256 + bci] = acc[q];
}

// ---------------------------------------------------------------------------
// K_einsum: D[bco][mode] = (1/TX) * sum_ci C[mode][b,ci] * W[mode][ci,co]
// Weights now coalesced via g_W.
// ---------------------------------------------------------------------------
__global__ void __launch_bounds__(256) k_einsum() {
    __shared__ float2 Cs[256];
    __shared__ float2 Ws[1024];
    const int tid = threadIdx.x;
    const int mode = blockIdx.x;
    Cs[tid] = g_C[(size_t)mode*256 + tid];
#pragma unroll
    for (int i = 0; i < 4; i++)
        Ws[tid + i*256] = g_W[(size_t)mode*1024 + tid + i*256];
    __syncthreads();
    const int b = tid >> 5, co = tid & 31;
    float2 acc = make_float2(0.f, 0.f);
#pragma unroll
    for (int ci = 0; ci < 32; ci++) {
        float2 c = Cs[b*32 + ci];
        float2 wv = Ws[ci*32 + co];
        acc.x += c.x*wv.x - c.y*wv.y;
        acc.y += c.x*wv.y + c.y*wv.x;
    }
    const float INV_TX = 1.0f / (128.0f * 256.0f);
    g_D[(size_t)tid*1024 + mode] = make_float2(acc.x*INV_TX, acc.y*INV_TX);
}

// ---------------------------------------------------------------------------
// K_inv: fused inverse. Block = (bco, t-half h) (512 blocks, 256 threads).
//  Phase 1: T-inverse (32 corner modes -> 64 t of this half) into Hs[t][rem]
//  Phase 2: loop 8 chunks of 8 t: X-inverse (16 modes -> 256 x) + irfft-P,
//           coalesced float4 stores.
// ---------------------------------------------------------------------------
__global__ void __launch_bounds__(256) k_inv(float* __restrict__ out) {
    extern __shared__ float2 dyn[];
    float2* Hs = dyn;                // [64][33] : Hs[t_local][rem]
    float2* gb = dyn + 64*33;        // [8][2][264]
    __shared__ float2 Ds[32][33];    // [rem][j]
    __shared__ float2 tw[256];       // e^{+2pi i n/256}
    __shared__ float2 tab[128];      // e^{+2pi i n/128}

    const int tid = threadIdx.x;
    {
        float sv, cv;
        __sincosf(6.283185307179586f * (float)tid * (1.0f/256.0f), &sv, &cv);
        tw[tid] = make_float2(cv, sv);
        if (tid < 128) {
            __sincosf(6.283185307179586f * (float)tid * (1.0f/128.0f), &sv, &cv);
            tab[tid] = make_float2(cv, sv);
        }
    }
    const int bco = blockIdx.x >> 1;
    const int h   = blockIdx.x & 1;

    const float2* src = g_D + (size_t)bco*1024;
#pragma unroll
    for (int i = 0; i < 4; i++) {
        int idx = tid + i*256;
        Ds[idx & 31][idx >> 5] = src[idx];
    }
    __syncthreads();

    const int w = tid >> 5, ln = tid & 31;
    {
        const int l = ln >> 3, b = ln & 7;
        const int rem = w*4 + l;
        float2 S[16];
#pragma unroll
        for (int r = 0; r < 16; r++) {
            float2 d0 = Ds[rem][r];
            float2 d1 = Ds[rem][r+16];
            float2 t0 = tab[(b*r) & 127];
            float2 t1 = tab[(b*(r+112)) & 127];
            S[r].x = d0.x*t0.x - d0.y*t0.y + d1.x*t1.x - d1.y*t1.y;
            S[r].y = d0.x*t0.y + d0.y*t0.x + d1.x*t1.y + d1.y*t1.x;
        }
        fft16<1>(S);                 // S[a] = H_{8a+b}
#pragma unroll
        for (int a = 0; a < 16; a++) {
            if ((a >> 3) == h)
                Hs[(8*(a - h*8) + b)*33 + rem] = S[a];
        }
    }
    __syncthreads();

    const int b_ = ln & 15;
    const int kp = ln >> 4;
    const float TH = 1.0f / 3.0f;
    const float SQ3 = 1.7320508075688772f;
    float2* gw0 = gb + w*528;        // this warp's kp=0 plane
    float2* gw  = gw0 + kp*264;

    for (int c = 0; c < 8; c++) {
        const int tl = c*8 + w;      // local t 0..63
        float2 v[16];
#pragma unroll
        for (int k = 0; k < 16; k++)
            v[k] = cmulf(Hs[tl*33 + k*2 + kp], tw[k*b_]);
        fft16<1>(v);
        const int pbase = (b_ >> 3) + (b_ & 7)*33;
#pragma unroll
        for (int a = 0; a < 16; a++)
            gw[pbase + 2*a] = v[a];
        __syncwarp();

        float f[24];
#pragma unroll
        for (int j = 0; j < 8; j++) {
            float2 g0 = gw0[ln + 33*j];
            float2 g1 = gw0[264 + ln + 33*j];
            float r = g0.x;
            f[3*j+0] = (r + 2.f*g1.x) * TH;
            f[3*j+1] = (r - g1.x - SQ3*g1.y) * TH;
            f[3*j+2] = (r - g1.x + SQ3*g1.y) * TH;
        }
        float4* op = (float4*)(out + ((size_t)bco*T_ + h*64 + tl)*768 + 24*ln);
#pragma unroll
        for (int q = 0; q < 6; q++)
            op[q] = make_float4(f[4*q], f[4*q+1], f[4*q+2], f[4*q+3]);
        __syncwarp();                // before next chunk overwrites gb (warp-local)
    }
}

extern "C" void kernel_launch(void* const* d_in, const int* in_sizes, int n_in,
                              void* d_out, int out_size) {
    const float* x   = (const float*)d_in[0];
    const float* w1r = (const float*)d_in[1];
    const float* w1i = (const float*)d_in[2];
    const float* w2r = (const float*)d_in[3];
    const float* w2i = (const float*)d_in[4];
    float* out = (float*)d_out;

    const int FWD_SMEM = (8*544 + 128*34) * (int)sizeof(float2);   // 69632
    const int INV_SMEM = (64*33 + 8*2*264) * (int)sizeof(float2);  // 50688
    cudaFuncSetAttribute(k_fwd, cudaFuncAttributeMaxDynamicSharedMemorySize, FWD_SMEM);
    cudaFuncSetAttribute(k_inv, cudaFuncAttributeMaxDynamicSharedMemorySize, INV_SMEM);

    k_wt    <<<dim3(32, 32), 256>>>(w1r, w1i, w2r, w2i);
    k_fwd   <<<256, 256, FWD_SMEM>>>(x);
    k_einsum<<<1024, 256>>>();
    k_inv   <<<512, 256, INV_SMEM>>>(out);
}

// round 7
// speedup vs baseline: 1.6519x; 1.6519x over previous
#include <cuda_runtime.h>
#include <cstdint>

// x: [B=8, Ci=32, T=128, X=256, P=3] f32
// w*: [Ci=32, Co=32, 16, 16, 3] f32
// out: [8, 32, 128, 256, 3] f32
#define B_  8
#define CI_ 32
#define CO_ 32
#define T_  128
#define X_  256
#define P_  3
#define KX_ 16
#define KT_ 32
#define KP_ 2

__device__ float2 g_A[B_*CI_*KX_*KP_*T_];   // [bci][kx][kp][t]
__device__ float2 g_C[KT_*KX_*KP_*B_*CI_];  // [mode][bci]
__device__ float2 g_D[B_*CO_*KT_*KX_*KP_];  // [bco][mode]
__device__ float2 g_H[B_*CO_*T_*KX_*KP_];   // [bco][t][rem]
__device__ float2 g_W[1024*1024];           // [mode][e=ci*32+co]

__device__ __forceinline__ float2 cmulf(float2 a, float2 b) {
    return make_float2(a.x*b.x - a.y*b.y, a.x*b.y + a.y*b.x);
}

// In-register radix-2 FFT-16. SGN=-1: forward; SGN=+1: inverse (unscaled).
template<int SGN>
__device__ __forceinline__ void fft16(float2 v[16]) {
    float2 tmp;
#define SW_(i,j) { tmp=v[i]; v[i]=v[j]; v[j]=tmp; }
    SW_(1,8) SW_(2,4) SW_(3,12) SW_(5,10) SW_(7,14) SW_(11,13)
#undef SW_
    const float Ct[8] = {1.f, 0.92387953251f, 0.70710678119f, 0.38268343236f,
                         0.f, -0.38268343236f, -0.70710678119f, -0.92387953251f};
    const float St[8] = {0.f, 0.38268343236f, 0.70710678119f, 0.92387953251f,
                         1.f, 0.92387953251f, 0.70710678119f, 0.38268343236f};
#pragma unroll
    for (int m = 2; m <= 16; m <<= 1) {
        const int half = m >> 1;
        const int step = 16 / m;
#pragma unroll
        for (int k0 = 0; k0 < 16; k0 += m) {
#pragma unroll
            for (int j = 0; j < half; j++) {
                float2 wt = make_float2(Ct[j*step], (float)SGN * St[j*step]);
                float2 t = cmulf(v[k0+j+half], wt);
                float2 u = v[k0+j];
                v[k0+j]      = make_float2(u.x + t.x, u.y + t.y);
                v[k0+j+half] = make_float2(u.x - t.x, u.y - t.y);
            }
        }
    }
}

// ---------------------------------------------------------------------------
// K0: weight transpose -> g_W[mode][e], coalesced writes.
// ---------------------------------------------------------------------------
__global__ void __launch_bounds__(256) k_wt(const float* __restrict__ w1r, const float* __restrict__ w1i,
                                           const float* __restrict__ w2r, const float* __restrict__ w2i) {
    __shared__ float sre[32][49];
    __shared__ float sim[32][49];
    const int kt = blockIdx.x;          // 0..31
    const int e0 = blockIdx.y * 32;
    const float* wr = (kt < 16) ? w1r : w2r;
    const float* wi = (kt < 16) ? w1i : w2i;
    const int ktw = kt & 15;
    const int tid = threadIdx.x;
    for (int j = tid; j < 32*48; j += 256) {
        int el = j / 48, m = j % 48;
        size_t src = (size_t)(e0 + el)*768 + ktw*48 + m;
        sre[el][m] = wr[src];
        sim[el][m] = wi[src];
    }
    __syncthreads();
    for (int idx = tid; idx < 1024; idx += 256) {
        int ml = idx >> 5, el = idx & 31;    // ml = kx*2+kp
        int kx = ml >> 1, kp = ml & 1;
        int m = kx*3 + kp;
        g_W[((size_t)kt*32 + ml)*1024 + e0 + el] = make_float2(sre[el][m], sim[el][m]);
    }
}

// ---------------------------------------------------------------------------
// K1: forward P-stage (rfft3 -> 2 modes) + pruned X-DFT (256 -> 16 modes)
// ---------------------------------------------------------------------------
__global__ void __launch_bounds__(256) k_fwd_px(const float* __restrict__ x) {
    __shared__ float2 region[8][544];
    __shared__ float2 tw[256];          // e^{-2pi i n/256}
    __shared__ float2 outstage[8][32];

    const int tid = threadIdx.x;
    {
        float sv, cv;
        __sincosf(-6.283185307179586f * (float)tid * (1.0f/256.0f), &sv, &cv);
        tw[tid] = make_float2(cv, sv);
    }
    const int bci = blockIdx.x >> 4;
    const int t0  = (blockIdx.x & 15) << 3;

    const float4* src = (const float4*)(x + (size_t)(bci*T_ + t0) * (X_*P_));
#pragma unroll
    for (int i = 0; i < 6; i++) {
        int idx = tid + i*256;
        float4 vv = src[idx];
        int fl = idx * 4;
        int line = fl / 768, off = fl % 768;
        *(float4*)((float*)region + line*1088 + off) = vv;
    }
    __syncthreads();

    const int w  = tid >> 5;
    const int ln = tid & 31;
    const int b_ = ln & 15;
    const int kp = ln >> 4;

    const float* rp = (const float*)region[w];
    float2 v[16];
#pragma unroll
    for (int a = 0; a < 16; a++) {
        int base = (a*16 + b_) * 3;
        float xa = rp[base], xb = rp[base+1], xc = rp[base+2];
        if (kp == 0) v[a] = make_float2(xa + xb + xc, 0.f);
        else         v[a] = make_float2(xa - 0.5f*(xb+xc), 0.8660254037844386f*(xc - xb));
    }
    __syncwarp();
    fft16<-1>(v);

    float2* trb = region[w];
#pragma unroll
    for (int k = 0; k < 16; k++) {
        float2 z = cmulf(v[k], tw[b_*k]);
        trb[b_*33 + kp*16 + k] = z;
    }
    __syncwarp();

    const int ko = ln & 15, kpo = ln >> 4;
    float2 acc = make_float2(0.f, 0.f);
#pragma unroll
    for (int b = 0; b < 16; b++) {
        float2 z = trb[b*33 + kpo*16 + ko];
        acc.x += z.x; acc.y += z.y;
    }
    outstage[w][ln] = acc;
    __syncthreads();

    const int idx = tid >> 3;
    const int tt  = tid & 7;
    const int k   = idx & 15, kpp = idx >> 4;
    g_A[(((size_t)bci*KX_ + k)*KP_ + kpp)*T_ + t0 + tt] = outstage[tt][kpp*16 + k];
}

// ---------------------------------------------------------------------------
// K2: forward T-DFT (128 -> 32 corner modes), radix split T = 8a + b.
// ---------------------------------------------------------------------------
__global__ void __launch_bounds__(128) k_fwd_t() {
    __shared__ float2 tab[128];       // e^{-2pi i n/128}
    __shared__ float2 reg[4][544];
    const int tid = threadIdx.x;
    {
        float sv, cv;
        __sincosf(-6.283185307179586f * (float)tid * (1.0f/128.0f), &sv, &cv);
        tab[tid] = make_float2(cv, sv);
    }
    const int bci = blockIdx.x >> 1;
    const int h   = blockIdx.x & 1;

    const float4* src = (const float4*)(g_A + ((size_t)bci*32 + h*16)*128);
#pragma unroll
    for (int i = 0; i < 8; i++) {
        int idx = tid + i*128;
        float4 vv = src[idx];
        int f2i = idx*2;
        int line = f2i >> 7, t = f2i & 127;
        *(float4*)&reg[line>>2][(line&3)*136 + t] = vv;
    }
    __syncthreads();

    const int w = tid >> 5, ln = tid & 31;
    const int l = ln >> 3, b = ln & 7;
    float2* R = reg[w];

    float2 v[16];
#pragma unroll
    for (int a = 0; a < 16; a++) v[a] = R[l*136 + a*8 + b];
    __syncwarp();
    fft16<-1>(v);
#pragma unroll
    for (int k = 0; k < 16; k++) R[ln*17 + k] = v[k];
    __syncwarp();

    const int o  = ln;
    const int f  = (o < 16) ? o : (o + 96);
    const int km = o & 15;
    float2 acc[4];
#pragma unroll
    for (int q = 0; q < 4; q++) acc[q] = make_float2(0.f, 0.f);
#pragma unroll
    for (int bb = 0; bb < 8; bb++) {
        float2 twv = tab[(bb*f) & 127];
#pragma unroll
        for (int q = 0; q < 4; q++) {
            float2 z = R[(q*8 + bb)*17 + km];
            acc[q].x += z.x*twv.x - z.y*twv.y;
            acc[q].y += z.x*twv.y + z.y*twv.x;
        }
    }
#pragma unroll
    for (int q = 0; q < 4; q++) {
        int rem = h*16 + w*4 + q;
        g_C[((size_t)o*32 + rem)*256 + bci] = acc[q];
    }
}

// ---------------------------------------------------------------------------
// K3: coalesced einsum via g_W: D[bco][mode] = (1/TX) sum_ci C[mode][b,ci]W[mode][ci,co]
// ---------------------------------------------------------------------------
__global__ void __launch_bounds__(256) k_einsum() {
    __shared__ float2 Cs[256];
    __shared__ float2 Ws[1024];
    const int tid = threadIdx.x;
    const int mode = blockIdx.x;
    Cs[tid] = g_C[(size_t)mode*256 + tid];
#pragma unroll
    for (int i = 0; i < 4; i++)
        Ws[tid + i*256] = g_W[(size_t)mode*1024 + tid + i*256];
    __syncthreads();
    const int b = tid >> 5, co = tid & 31;
    float2 acc = make_float2(0.f, 0.f);
#pragma unroll
    for (int ci = 0; ci < 32; ci++) {
        float2 c = Cs[b*32 + ci];
        float2 wv = Ws[ci*32 + co];
        acc.x += c.x*wv.x - c.y*wv.y;
        acc.y += c.x*wv.y + c.y*wv.x;
    }
    const float INV_TX = 1.0f / (128.0f * 256.0f);
    g_D[(size_t)tid*1024 + mode] = make_float2(acc.x*INV_TX, acc.y*INV_TX);
}

// ---------------------------------------------------------------------------
// K4: inverse T (32 corner modes -> 128 t), radix split t = 8a + b.
// ---------------------------------------------------------------------------
__global__ void __launch_bounds__(128) k_inv_t() {
    __shared__ float2 tab[128];       // e^{+2pi i n/128}
    __shared__ float2 Ds[16][33];
    __shared__ float2 Hs[128][17];
    const int tid = threadIdx.x;
    {
        float sv, cv;
        __sincosf(6.283185307179586f * (float)tid * (1.0f/128.0f), &sv, &cv);
        tab[tid] = make_float2(cv, sv);
    }
    const int bco = blockIdx.x >> 1;
    const int h   = blockIdx.x & 1;

    const float2* src = g_D + (size_t)bco*1024;
#pragma unroll
    for (int i = 0; i < 4; i++) {
        int idx = tid + i*128;
        int j = idx >> 4, r = idx & 15;
        Ds[r][j] = src[j*32 + h*16 + r];
    }
    __syncthreads();

    const int w = tid >> 5, ln = tid & 31;
    const int l = ln >> 3, b = ln & 7;
    const int rem = w*4 + l;

    float2 S[16];
#pragma unroll
    for (int r = 0; r < 16; r++) {
        float2 d0 = Ds[rem][r];
        float2 d1 = Ds[rem][r+16];
        float2 t0 = tab[(b*r) & 127];
        float2 t1 = tab[(b*(r+112)) & 127];
        S[r].x = d0.x*t0.x - d0.y*t0.y + d1.x*t1.x - d1.y*t1.y;
        S[r].y = d0.x*t0.y + d0.y*t0.x + d1.x*t1.y + d1.y*t1.x;
    }
    fft16<1>(S);
#pragma unroll
    for (int a = 0; a < 16; a++) Hs[a*8 + b][rem] = S[a];
    __syncthreads();

    float4* dst = (float4*)(g_H + (size_t)bco*4096);
#pragma unroll
    for (int i = 0; i < 8; i++) {
        int idx = tid + i*128;
        int t = idx >> 3, q = idx & 7;
        float2 a0 = Hs[t][q*2], a1 = Hs[t][q*2 + 1];
        dst[t*16 + h*8 + q] = make_float4(a0.x, a0.y, a1.x, a1.y);
    }
}

// ---------------------------------------------------------------------------
// K5: inverse X (16 modes -> 256 x) + irfft over P, permuted store staging.
// ---------------------------------------------------------------------------
__global__ void __launch_bounds__(256) k_inv_xp(float* __restrict__ out) {
    __shared__ float2 tw[256];        // e^{+2pi i n/256}
    __shared__ float2 Hsm[8][32];
    __shared__ float2 gb[8][2][264];
    const int tid = threadIdx.x;
    {
        float sv, cv;
        __sincosf(6.283185307179586f * (float)tid * (1.0f/256.0f), &sv, &cv);
        tw[tid] = make_float2(cv, sv);
    }
    const int bco = blockIdx.x >> 4;
    const int t0  = (blockIdx.x & 15) << 3;
    Hsm[tid>>5][tid&31] = g_H[((size_t)bco*T_ + t0 + (tid>>5))*32 + (tid&31)];
    __syncthreads();

    const int w  = tid >> 5;
    const int ln = tid & 31;
    const int b_ = ln & 15;
    const int kp = ln >> 4;

    float2 v[16];
#pragma unroll
    for (int k = 0; k < 16; k++)
        v[k] = cmulf(Hsm[w][k*2 + kp], tw[k*b_]);
    fft16<1>(v);
    const int pbase = (b_ >> 3) + (b_ & 7)*33;
#pragma unroll
    for (int a = 0; a < 16; a++)
        gb[w][kp][pbase + 2*a] = v[a];
    __syncwarp();

    float f[24];
    const float TH = 1.0f / 3.0f;
    const float SQ3 = 1.7320508075688772f;
#pragma unroll
    for (int j = 0; j < 8; j++) {
        float2 g0 = gb[w][0][ln + 33*j];
        float2 g1 = gb[w][1][ln + 33*j];
        float r = g0.x;
        f[3*j+0] = (r + 2.f*g1.x) * TH;
        f[3*j+1] = (r - g1.x - SQ3*g1.y) * TH;
        f[3*j+2] = (r - g1.x + SQ3*g1.y) * TH;
    }
    float4* op = (float4*)(out + ((size_t)bco*T_ + t0 + w)*768 + 24*ln);
#pragma unroll
    for (int q = 0; q < 6; q++)
        op[q] = make_float4(f[4*q], f[4*q+1], f[4*q+2], f[4*q+3]);
}

extern "C" void kernel_launch(void* const* d_in, const int* in_sizes, int n_in,
                              void* d_out, int out_size) {
    const float* x   = (const float*)d_in[0];
    const float* w1r = (const float*)d_in[1];
    const float* w1i = (const float*)d_in[2];
    const float* w2r = (const float*)d_in[3];
    const float* w2i = (const float*)d_in[4];
    float* out = (float*)d_out;

    k_wt    <<<dim3(32, 32), 256>>>(w1r, w1i, w2r, w2i);
    k_fwd_px<<<4096, 256>>>(x);
    k_fwd_t <<<512, 128>>>();
    k_einsum<<<1024, 256>>>();
    k_inv_t <<<512, 128>>>();
    k_inv_xp<<<4096, 256>>>(out);
}